// round 10
// baseline (speedup 1.0000x reference)
#include <cuda_runtime.h>

#define NQ       10
#define DIM      1024
#define NLAYERS  4
#define NT       64           // 64 threads = 2 warps = one state-pair (2 batch elems)
#define PI_F     3.14159265358979323846f

typedef unsigned long long u64;

// ---- packed f32x2 helpers (batch0 in lo, batch1 in hi) ----
__device__ __forceinline__ u64 pk2(float lo, float hi) {
    u64 r; asm("mov.b64 %0, {%1, %2};" : "=l"(r) : "f"(lo), "f"(hi)); return r;
}
__device__ __forceinline__ void upk2(u64 v, float& lo, float& hi) {
    asm("mov.b64 {%0, %1}, %2;" : "=f"(lo), "=f"(hi) : "l"(v));
}
__device__ __forceinline__ u64 fma2(u64 a, u64 b, u64 c) {
    u64 d; asm("fma.rn.f32x2 %0, %1, %2, %3;" : "=l"(d) : "l"(a), "l"(b), "l"(c)); return d;
}
__device__ __forceinline__ u64 mul2(u64 a, u64 b) {
    u64 d; asm("mul.rn.f32x2 %0, %1, %2;" : "=l"(d) : "l"(a), "l"(b)); return d;
}
__device__ __forceinline__ u64 add2(u64 a, u64 b) {
    u64 d; asm("add.rn.f32x2 %0, %1, %2;" : "=l"(d) : "l"(a), "l"(b)); return d;
}
__device__ __forceinline__ u64 neg2(u64 v) { return v ^ 0x8000000080000000ULL; }

// packed complex multiply: (zr,zi) = (ar,ai)*(br,bi)
__device__ __forceinline__ void cmul2(u64 ar, u64 ai, u64 br, u64 bi, u64& zr, u64& zi) {
    zr = fma2(ar, br, neg2(mul2(ai, bi)));
    zi = fma2(ar, bi, mul2(ai, br));
}

// ---- scalar complex helpers (matrix construction only) ----
__device__ __forceinline__ float2 cmul(float2 a, float2 b) {
    return make_float2(fmaf(a.x, b.x, -a.y * b.y), fmaf(a.x, b.y, a.y * b.x));
}
__device__ __forceinline__ float2 cadd(float2 a, float2 b) { return make_float2(a.x + b.x, a.y + b.y); }
__device__ __forceinline__ float2 csub(float2 a, float2 b) { return make_float2(a.x - b.x, a.y - b.y); }
__device__ __forceinline__ float2 cscale(float s, float2 a) { return make_float2(s * a.x, s * a.y); }

// smem swizzle: phys(j) = j ^ s(j>>5), s(a) = (a&15) | ((a&8)<<1).
// Conflict-free for all three transpose patterns (unchanged from R7/R9).
__device__ __forceinline__ int phys(int j) {
    int a = j >> 5;
    return j ^ ((a & 15) | ((a & 8) << 1));
}

// Fused per-wire gate G = [c, -A; B, C] (c real; A,B,C complex), applied on
// register bit g over 8 disjoint pairs. 14 packed ops/pair, no LOP.
// Coefficient pack layout (ulonglong2[6]):
//   [0]=(c,Ar) [1]=(nAr,Ai) [2]=(nAi,Br) [3]=(Bi,nBi) [4]=(Cr,Ci) [5]=(nCi,-)
#define APPLY_G(COptr, g) do {                                                 \
    const ulonglong2* CO_ = (COptr);                                           \
    const ulonglong2 q0=CO_[0], q1=CO_[1], q2=CO_[2], q3=CO_[3],               \
                     q4=CO_[4], q5=CO_[5];                                     \
    const u64 c_=q0.x, Ar_=q0.y, nAr_=q1.x, Ai_=q1.y, nAi_=q2.x, Br_=q2.y,    \
              Bi_=q3.x, nBi_=q3.y, Cr_=q4.x, Ci_=q4.y, nCi_=q5.x;             \
    (void)Ar_;                                                                 \
    const int bm_ = 1 << (g), lo_ = bm_ - 1;                                   \
    _Pragma("unroll") for (int p_ = 0; p_ < 8; ++p_) {                         \
        const int i0_ = ((p_ & ~lo_) << 1) | (p_ & lo_);                       \
        const int i1_ = i0_ | bm_;                                             \
        u64 b0r = fma2(c_,  re[i0_], fma2(nAr_, re[i1_], mul2(Ai_,  im[i1_])));\
        u64 b0i = fma2(c_,  im[i0_], fma2(nAr_, im[i1_], mul2(nAi_, re[i1_])));\
        u64 b1r = fma2(Br_, re[i0_], fma2(nBi_, im[i0_],                       \
                      fma2(Cr_, re[i1_], mul2(nCi_, im[i1_]))));               \
        u64 b1i = fma2(Br_, im[i0_], fma2(Bi_,  re[i0_],                       \
                      fma2(Cr_, im[i1_], mul2(Ci_,  re[i1_]))));               \
        re[i0_] = b0r; im[i0_] = b0i; re[i1_] = b1r; im[i1_] = b1i;            \
    }                                                                          \
} while (0)

__global__ __launch_bounds__(NT)
void quantum_layer_kernel(const float* __restrict__ x,
                          const float* __restrict__ weight,
                          float* __restrict__ out)
{
    __shared__ ulonglong2 sv[DIM];            // 16 KB: (re_pk2, im_pk2)
    __shared__ ulonglong2 coef[NLAYERS][NQ][6]; // fused gate coeffs: 3.75 KB
    __shared__ unsigned short scat[DIM];      // CNOT-ring scatter LUT (swizzled)
    __shared__ u64 wred[2][NQ];               // cross-warp measurement reduce

    const int t  = threadIdx.x;               // 0..63
    const int b0 = blockIdx.x * 2, b1 = b0 + 1;

    // ---- CNOT-ring: st'[j] = st[p(j)]. scat[p(j)] = phys(j).
    for (int j = t; j < DIM; j += NT) {
        int src = j;
        src ^= (src & 1) << 9;                         // CNOT(9,0)
        #pragma unroll
        for (int q = 8; q >= 0; --q) {                 // CNOT(q,q+1)
            int cb = 9 - q, tb = 8 - q;
            src ^= ((src >> cb) & 1) << tb;
        }
        scat[src] = (unsigned short)phys(j);
    }

    // ---- per-wire fused matrix -> 4-coefficient gate [c, -A; B, C]
    // M = [u, -conj(v); v, conj(u)] (SU(2)); G = e^{-i*arg(u)} * M:
    //   c = |u|, ph = conj(u)/c, A = conj(v)*ph, B = v*ph, C = conj(u)*ph.
    if (t < NQ) {
        const int w = t;
        float ang[2];
        ang[0] = tanhf(x[b0 * NQ + w]) * PI_F;
        ang[1] = tanhf(x[b1 * NQ + w]) * PI_F;
        for (int l = 0; l < NLAYERS; ++l) {
            float th1 = weight[(l * NQ + w) * 3 + 0];
            float th2 = weight[(l * NQ + w) * 3 + 1];
            float th3 = weight[(l * NQ + w) * 3 + 2];
            float cc[2], Arr[2], Aii[2], Brr[2], Bii[2], Crr[2], Cii[2];
            #pragma unroll
            for (int bb = 0; bb < 2; ++bb) {
                float s0, c0, s1, c1, s2, c2, s3, c3;
                __sincosf(0.5f * ang[bb], &s0, &c0);
                __sincosf(0.5f * th1, &s1, &c1);
                __sincosf(0.5f * th2, &s2, &c2);
                __sincosf(0.5f * th3, &s3, &c3);
                float2 d1m = make_float2(c1, -s1), d1p = make_float2(c1, s1);
                float2 d3m = make_float2(c3, -s3), d3p = make_float2(c3, s3);
                // u = m00, v = m10 of the fused SU(2) matrix
                float2 u = cmul(d3m, csub(cscale(c2 * c0, d1m), cscale(s2 * s0, d1p)));
                float2 v = cmul(d3p, cadd(cscale(s2 * c0, d1m), cscale(c2 * s0, d1p)));
                float c = sqrtf(fmaf(u.x, u.x, u.y * u.y));
                float phr, phi;
                if (c > 1e-20f) { float inv = 1.0f / c; phr = u.x * inv; phi = -u.y * inv; }
                else            { phr = 1.0f; phi = 0.0f; }
                cc[bb]  = c;
                Arr[bb] = v.x * phr + v.y * phi;           // A = conj(v)*ph
                Aii[bb] = fmaf(v.x, phi, -v.y * phr);
                Brr[bb] = fmaf(v.x, phr, -v.y * phi);      // B = v*ph
                Bii[bb] = v.x * phi + v.y * phr;
                Crr[bb] = u.x * phr + u.y * phi;           // C = conj(u)*ph
                Cii[bb] = fmaf(u.x, phi, -u.y * phr);
            }
            ulonglong2* dst = coef[l][w];
            u64 Ar = pk2(Arr[0], Arr[1]), Ai = pk2(Aii[0], Aii[1]);
            u64 Br = pk2(Brr[0], Brr[1]), Bi = pk2(Bii[0], Bii[1]);
            u64 Cr = pk2(Crr[0], Crr[1]), Ci = pk2(Cii[0], Cii[1]);
            dst[0] = make_ulonglong2(pk2(cc[0], cc[1]), Ar);
            dst[1] = make_ulonglong2(neg2(Ar), Ai);
            dst[2] = make_ulonglong2(neg2(Ai), Br);
            dst[3] = make_ulonglong2(Bi, neg2(Bi));
            dst[4] = make_ulonglong2(Cr, Ci);
            dst[5] = make_ulonglong2(neg2(Ci), 0ULL);
        }
    }
    __syncthreads();

    // preload layer-invariant scatter addresses (16 u16 -> regs)
    int sc[16];
    #pragma unroll
    for (int r = 0; r < 16; ++r) sc[r] = scat[(r << 6) | t];

    // ---- state: 16 amps/thread, three arrangements per layer:
    //  A: j = (t<<4)|r                 r bits 0..3 = wires 9..6
    //  B: j = (t>>4)<<8|(r<<4)|(t&15)  r bits 0..3 = wires 5..2
    //  C: j = (r<<6)|t                 r bits 2,3  = wires 1,0
    u64 re[16], im[16];

    const int tbhi = (t >> 4) << 8, tblo = t & 15;

    #pragma unroll 1
    for (int l = 0; l < NLAYERS; ++l) {
        if (l == 0) {
            // |0..0>: A-group gates from basis state -> column-0 product,
            // nonzero only on thread 0. Column 0 of G = (c, B).
            #pragma unroll
            for (int i = 0; i < 16; ++i) { re[i] = 0ULL; im[i] = 0ULL; }
            if (t == 0) {
                #pragma unroll
                for (int r = 0; r < 16; ++r) {
                    u64 ar = pk2(1.0f, 1.0f), ai = 0ULL;
                    #pragma unroll
                    for (int g = 0; g < 4; ++g) {
                        const ulonglong2* CO = coef[0][9 - g];
                        u64 er, ei;
                        if ((r >> g) & 1) { er = CO[2].y; ei = CO[3].x; }  // B
                        else              { er = CO[0].x; ei = 0ULL; }     // c
                        u64 nr, ni;
                        cmul2(ar, ai, er, ei, nr, ni);
                        ar = nr; ai = ni;
                    }
                    re[r] = ar; im[r] = ai;
                }
            }
        } else {
            // load A (own slots — written by scat store of previous layer)
            #pragma unroll
            for (int r = 0; r < 16; ++r) {
                ulonglong2 v = sv[phys((t << 4) | r)];
                re[r] = v.x; im[r] = v.y;
            }
            APPLY_G(coef[l][9], 0);
            APPLY_G(coef[l][8], 1);
            APPLY_G(coef[l][7], 2);
            APPLY_G(coef[l][6], 3);
        }
        #pragma unroll
        for (int r = 0; r < 16; ++r)
            sv[phys((t << 4) | r)] = make_ulonglong2(re[r], im[r]);
        __syncthreads();

        // ---- group B: wires 5..2 on reg bits 0..3
        #pragma unroll
        for (int r = 0; r < 16; ++r) {
            ulonglong2 v = sv[phys(tbhi | (r << 4) | tblo)];
            re[r] = v.x; im[r] = v.y;
        }
        APPLY_G(coef[l][5], 0);
        APPLY_G(coef[l][4], 1);
        APPLY_G(coef[l][3], 2);
        APPLY_G(coef[l][2], 3);
        #pragma unroll
        for (int r = 0; r < 16; ++r)
            sv[phys(tbhi | (r << 4) | tblo)] = make_ulonglong2(re[r], im[r]);
        __syncthreads();

        // ---- group C: wires 1,0 on reg bits 2,3
        #pragma unroll
        for (int r = 0; r < 16; ++r) {
            ulonglong2 v = sv[phys((r << 6) | t)];
            re[r] = v.x; im[r] = v.y;
        }
        if (l < NLAYERS - 1) __syncthreads();  // all C loads done before scatter
        APPLY_G(coef[l][1], 2);
        APPLY_G(coef[l][0], 3);
        if (l < NLAYERS - 1) {
            #pragma unroll
            for (int r = 0; r < 16; ++r)
                sv[sc[r]] = make_ulonglong2(re[r], im[r]);
            __syncthreads();
        }
    }

    // ---- measurement in arrangement C: amp x = (r<<6)|t.
    // Final CNOT ring folded into signs: bit k of pinv(x) = parity(x & mask_k),
    // mask_k = bits k..9 (k=0..8), mask_9 = 0x1FF.
    #pragma unroll
    for (int i = 0; i < 16; ++i)
        re[i] = fma2(re[i], re[i], mul2(im[i], im[i]));   // packed |amp|^2

    const u64 pone = pk2(1.0f, 1.0f), none = pk2(-1.0f, -1.0f);
    const int warp = t >> 5;
    const unsigned fullmask = 0xffffffffu;
    #pragma unroll
    for (int w = 0; w < NQ; ++w) {
        const int k = 9 - w;
        const unsigned mask = (k == 9) ? 0x1FFu : (0x3FFu & ~((1u << k) - 1u));
        const unsigned mr = (mask >> 6) & 15u, mt = mask & 63u;
        u64 acc = 0ULL;
        #pragma unroll
        for (int r = 0; r < 16; ++r)
            acc = fma2(re[r], (__popc((unsigned)r & mr) & 1) ? none : pone, acc);
        if (__popc((unsigned)t & mt) & 1) acc = neg2(acc);
        #pragma unroll
        for (int off = 16; off; off >>= 1) {
            u64 o = __shfl_xor_sync(fullmask, acc, off);
            acc = add2(acc, o);
        }
        if ((t & 31) == 0) wred[warp][w] = acc;
    }
    __syncthreads();
    if (t < NQ) {
        u64 s = add2(wred[0][t], wred[1][t]);
        float ra, rb; upk2(s, ra, rb);
        out[b0 * NQ + t] = ra;
        out[b1 * NQ + t] = rb;
    }
}

extern "C" void kernel_launch(void* const* d_in, const int* in_sizes, int n_in,
                              void* d_out, int out_size) {
    const float* x      = (const float*)d_in[0];   // (16384, 10) float32
    const float* weight = (const float*)d_in[1];   // (4, 10, 3)  float32
    float* out          = (float*)d_out;           // (16384, 10) float32
    const int batch  = in_sizes[0] / NQ;
    const int blocks = batch / 2;                  // 2 batch elems per block
    quantum_layer_kernel<<<blocks, NT>>>(x, weight, out);
}

// round 11
// speedup vs baseline: 1.0873x; 1.0873x over previous
#include <cuda_runtime.h>

#define NQ       10
#define DIM      1024
#define NLAYERS  4
#define NT       64           // 64 threads = 2 warps = one state-pair (2 batch elems)
#define PI_F     3.14159265358979323846f

typedef unsigned long long u64;

// ---- packed f32x2 helpers (batch0 in lo, batch1 in hi) ----
__device__ __forceinline__ u64 pk2(float lo, float hi) {
    u64 r; asm("mov.b64 %0, {%1, %2};" : "=l"(r) : "f"(lo), "f"(hi)); return r;
}
__device__ __forceinline__ void upk2(u64 v, float& lo, float& hi) {
    asm("mov.b64 {%0, %1}, %2;" : "=f"(lo), "=f"(hi) : "l"(v));
}
__device__ __forceinline__ u64 fma2(u64 a, u64 b, u64 c) {
    u64 d; asm("fma.rn.f32x2 %0, %1, %2, %3;" : "=l"(d) : "l"(a), "l"(b), "l"(c)); return d;
}
__device__ __forceinline__ u64 mul2(u64 a, u64 b) {
    u64 d; asm("mul.rn.f32x2 %0, %1, %2;" : "=l"(d) : "l"(a), "l"(b)); return d;
}
__device__ __forceinline__ u64 add2(u64 a, u64 b) {
    u64 d; asm("add.rn.f32x2 %0, %1, %2;" : "=l"(d) : "l"(a), "l"(b)); return d;
}
__device__ __forceinline__ u64 neg2(u64 v) { return v ^ 0x8000000080000000ULL; }
__device__ __forceinline__ u64 sub2(u64 a, u64 b) { return add2(a, neg2(b)); }

// ---- scalar complex helpers (matrix construction only) ----
__device__ __forceinline__ float2 cmul(float2 a, float2 b) {
    return make_float2(fmaf(a.x, b.x, -a.y * b.y), fmaf(a.x, b.y, a.y * b.x));
}
__device__ __forceinline__ float2 cadd(float2 a, float2 b) { return make_float2(a.x + b.x, a.y + b.y); }
__device__ __forceinline__ float2 csub(float2 a, float2 b) { return make_float2(a.x - b.x, a.y - b.y); }
__device__ __forceinline__ float2 cscale(float s, float2 a) { return make_float2(s * a.x, s * a.y); }

// smem swizzle: phys(j) = j ^ s(j>>5), s(a) = (a&15) | ((a&8)<<1).
__device__ __forceinline__ int phys(int j) {
    int a = j >> 5;
    return j ^ ((a & 15) | ((a & 8) << 1));
}

// real RY on register bit g: 8 disjoint pairs, 8 packed ops/pair
#define APPLY_RY(COptr, g) do {                                             \
    const ulonglong2 q_ = *(COptr);                                         \
    const u64 c_ = q_.x, s_ = q_.y, ns_ = neg2(s_);                         \
    const int bm_ = 1 << (g), lo_ = bm_ - 1;                                \
    _Pragma("unroll") for (int p_ = 0; p_ < 8; ++p_) {                      \
        const int i0_ = ((p_ & ~lo_) << 1) | (p_ & lo_);                    \
        const int i1_ = i0_ | bm_;                                          \
        u64 b0r = fma2(c_, re[i0_], mul2(ns_, re[i1_]));                    \
        u64 b0i = fma2(c_, im[i0_], mul2(ns_, im[i1_]));                    \
        u64 b1r = fma2(c_, re[i1_], mul2(s_,  re[i0_]));                    \
        u64 b1i = fma2(c_, im[i1_], mul2(s_,  im[i0_]));                    \
        re[i0_] = b0r; im[i0_] = b0i; re[i1_] = b1r; im[i1_] = b1i;         \
    }                                                                       \
} while (0)

// full-state diagonal event: multiply amp by prod over set bits of e^{i*theta_w}.
// FB = &F[l][0]; thread bit k -> wire (TW0-k); reg bit b -> wire (RW0-b).
// Per-event scalar normalizers are global phases -> dropped.
#define APPLY_DIAG(FB, TW0, RW0) do {                                       \
    u64 zr_ = pk2(1.0f, 1.0f), zi_ = 0ULL;                                  \
    _Pragma("unroll") for (int k_ = 0; k_ < 6; ++k_) {                      \
        const ulonglong2 f_ = (FB)[(TW0) - k_];                             \
        u64 nr_ = fma2(zr_, f_.x, neg2(mul2(zi_, f_.y)));                   \
        u64 ni_ = fma2(zr_, f_.y, mul2(zi_, f_.x));                         \
        if ((t >> k_) & 1) { zr_ = nr_; zi_ = ni_; }                        \
    }                                                                       \
    u64 wr_[16], wi_[16];                                                   \
    wr_[0] = zr_; wi_[0] = zi_;                                             \
    _Pragma("unroll") for (int b_ = 0; b_ < 4; ++b_) {                      \
        const ulonglong2 f_ = (FB)[(RW0) - b_];                             \
        _Pragma("unroll") for (int x_ = 0; x_ < 8; ++x_) {                  \
            if (x_ < (1 << b_)) {                                           \
                wr_[x_ | (1 << b_)] = fma2(wr_[x_], f_.x, neg2(mul2(wi_[x_], f_.y))); \
                wi_[x_ | (1 << b_)] = fma2(wr_[x_], f_.y, mul2(wi_[x_], f_.x));       \
            }                                                               \
        }                                                                   \
    }                                                                       \
    _Pragma("unroll") for (int r_ = 0; r_ < 16; ++r_) {                     \
        u64 nr_ = fma2(re[r_], wr_[r_], neg2(mul2(im[r_], wi_[r_])));       \
        u64 ni_ = fma2(re[r_], wi_[r_], mul2(im[r_], wr_[r_]));             \
        re[r_] = nr_; im[r_] = ni_;                                         \
    }                                                                       \
} while (0)

__global__ __launch_bounds__(NT)
void quantum_layer_kernel(const float* __restrict__ x,
                          const float* __restrict__ weight,
                          float* __restrict__ out)
{
    __shared__ ulonglong2 sv[DIM];            // 16 KB: (re_pk2, im_pk2)
    __shared__ ulonglong2 ry[NLAYERS][NQ];    // (c, s) RY(delta) coeffs, packed
    __shared__ ulonglong2 Fe[NLAYERS][NQ];    // e^{i*eps_w}  (cos, sin), packed
    __shared__ ulonglong2 Fg[NLAYERS][NQ];    // e^{i*gamma_w}
    __shared__ unsigned short scat[DIM];      // CNOT-ring scatter LUT (swizzled)
    __shared__ u64 wred[2][NQ];               // cross-warp measurement reduce

    const int t  = threadIdx.x;               // 0..63
    const int b0 = blockIdx.x * 2, b1 = b0 + 1;

    // ---- CNOT-ring: st'[j] = st[p(j)]. scat[p(j)] = phys(j).
    for (int j = t; j < DIM; j += NT) {
        int src = j;
        src ^= (src & 1) << 9;                         // CNOT(9,0)
        #pragma unroll
        for (int q = 8; q >= 0; --q) {                 // CNOT(q,q+1)
            int cb = 9 - q, tb = 8 - q;
            src ^= ((src >> cb) & 1) << tb;
        }
        scat[src] = (unsigned short)phys(j);
    }

    // ---- per-wire ZYZ: M = RZ(gamma)*RY(delta)*RZ(eps) (scalar prefactors are
    // global phases, dropped). c=|m00|, s=|m10|, gamma=av-au, eps=-av-au.
    if (t < NQ) {
        const int w = t;
        float ang[2];
        ang[0] = tanhf(x[b0 * NQ + w]) * PI_F;
        ang[1] = tanhf(x[b1 * NQ + w]) * PI_F;
        for (int l = 0; l < NLAYERS; ++l) {
            float th1 = weight[(l * NQ + w) * 3 + 0];
            float th2 = weight[(l * NQ + w) * 3 + 1];
            float th3 = weight[(l * NQ + w) * 3 + 2];
            float cc[2], ss[2], ger[2], gei[2], eer[2], eei[2];
            #pragma unroll
            for (int bb = 0; bb < 2; ++bb) {
                float s0, c0, s1, c1, s2, c2, s3, c3;
                __sincosf(0.5f * ang[bb], &s0, &c0);
                __sincosf(0.5f * th1, &s1, &c1);
                __sincosf(0.5f * th2, &s2, &c2);
                __sincosf(0.5f * th3, &s3, &c3);
                float2 d1m = make_float2(c1, -s1), d1p = make_float2(c1, s1);
                float2 d3m = make_float2(c3, -s3), d3p = make_float2(c3, s3);
                // u = m00, v = m10 of the fused SU(2) matrix
                float2 u = cmul(d3m, csub(cscale(c2 * c0, d1m), cscale(s2 * s0, d1p)));
                float2 v = cmul(d3p, cadd(cscale(s2 * c0, d1m), cscale(c2 * s0, d1p)));
                cc[bb] = sqrtf(fmaf(u.x, u.x, u.y * u.y));
                ss[bb] = sqrtf(fmaf(v.x, v.x, v.y * v.y));
                float au = atan2f(u.y, u.x);
                float av = atan2f(v.y, v.x);
                float sg, cg, se, ce;
                __sincosf(av - au, &sg, &cg);    // e^{i*gamma}
                __sincosf(-av - au, &se, &ce);   // e^{i*eps}
                ger[bb] = cg; gei[bb] = sg; eer[bb] = ce; eei[bb] = se;
            }
            ry[l][w] = make_ulonglong2(pk2(cc[0], cc[1]), pk2(ss[0], ss[1]));
            Fg[l][w] = make_ulonglong2(pk2(ger[0], ger[1]), pk2(gei[0], gei[1]));
            Fe[l][w] = make_ulonglong2(pk2(eer[0], eer[1]), pk2(eei[0], eei[1]));
        }
    }
    __syncthreads();

    // ---- state: 16 amps/thread, three arrangements per layer:
    //  A: j = (t<<4)|r                 r bits 0..3 = wires 9..6; t bits 0..5 = wires 5..0
    //  B: j = (t>>4)<<8|(r<<4)|(t&15)  r bits 0..3 = wires 5..2
    //  C: j = (r<<6)|t                 r bits 0..3 = wires 3..0; t bits 0..5 = wires 9..4
    //     (C-group RY gates act on wires 1,0 = reg bits 2,3)
    u64 re[16], im[16];

    const int tbhi = (t >> 4) << 8, tblo = t & 15;

    #pragma unroll 1
    for (int l = 0; l < NLAYERS; ++l) {
        // ===== arrangement A: D_eps(l) (l>=1; eps_0 is a global phase), RY wires 9..6
        if (l == 0) {
            // |0..0>: pure-RY column-0 products on thread 0 (real)
            #pragma unroll
            for (int i = 0; i < 16; ++i) { re[i] = 0ULL; im[i] = 0ULL; }
            if (t == 0) {
                #pragma unroll
                for (int r = 0; r < 16; ++r) {
                    u64 v = pk2(1.0f, 1.0f);
                    #pragma unroll
                    for (int g = 0; g < 4; ++g) {
                        const ulonglong2 q = ry[0][9 - g];
                        v = mul2(v, ((r >> g) & 1) ? q.y : q.x);
                    }
                    re[r] = v;
                }
            }
        } else {
            #pragma unroll
            for (int r = 0; r < 16; ++r) {
                ulonglong2 v = sv[phys((t << 4) | r)];
                re[r] = v.x; im[r] = v.y;
            }
            APPLY_DIAG(&Fe[l][0], 5, 9);       // eps: t bits->wires 5..0, r bits->wires 9..6
            APPLY_RY(&ry[l][9], 0);
            APPLY_RY(&ry[l][8], 1);
            APPLY_RY(&ry[l][7], 2);
            APPLY_RY(&ry[l][6], 3);
        }
        #pragma unroll
        for (int r = 0; r < 16; ++r)
            sv[phys((t << 4) | r)] = make_ulonglong2(re[r], im[r]);
        __syncthreads();

        // ===== arrangement B: RY wires 5..2
        #pragma unroll
        for (int r = 0; r < 16; ++r) {
            ulonglong2 v = sv[phys(tbhi | (r << 4) | tblo)];
            re[r] = v.x; im[r] = v.y;
        }
        APPLY_RY(&ry[l][5], 0);
        APPLY_RY(&ry[l][4], 1);
        APPLY_RY(&ry[l][3], 2);
        APPLY_RY(&ry[l][2], 3);
        #pragma unroll
        for (int r = 0; r < 16; ++r)
            sv[phys(tbhi | (r << 4) | tblo)] = make_ulonglong2(re[r], im[r]);
        __syncthreads();

        // ===== arrangement C: RY wires 1,0; D_gamma(l) (l<=2; gamma_3 invisible in |.|^2)
        #pragma unroll
        for (int r = 0; r < 16; ++r) {
            ulonglong2 v = sv[phys((r << 6) | t)];
            re[r] = v.x; im[r] = v.y;
        }
        APPLY_RY(&ry[l][1], 2);
        APPLY_RY(&ry[l][0], 3);
        if (l < NLAYERS - 1) {
            APPLY_DIAG(&Fg[l][0], 9, 3);       // gamma: t->wires 9..4, r->wires 3..0
            __syncthreads();                   // all C loads done before scatter
            #pragma unroll
            for (int r = 0; r < 16; ++r)
                sv[scat[(r << 6) | t]] = make_ulonglong2(re[r], im[r]);
            __syncthreads();
        }
    }

    // ---- measurement in arrangement C: amp x = (r<<6)|t.
    // Final CNOT ring folded into signs: sign_w(x) = parity(x & mask_{9-w}),
    // mask_k = bits k..9 (k<=8), mask_9 = 0x1FF.
    #pragma unroll
    for (int i = 0; i < 16; ++i)
        re[i] = fma2(re[i], re[i], mul2(im[i], im[i]));   // packed |amp|^2

    // r-parity partial sums: only mr in {15,14,12,7} occur.
    u64 S[8], A[8];
    #pragma unroll
    for (int i = 0; i < 8; ++i) { S[i] = add2(re[i], re[i + 8]); A[i] = sub2(re[i], re[i + 8]); }
    u64 S2[4], B4[4];
    #pragma unroll
    for (int i = 0; i < 4; ++i) { S2[i] = sub2(S[i], S[i + 4]); B4[i] = sub2(A[i], A[i + 4]); }
    u64 S21_0 = sub2(S2[0], S2[2]), S21_1 = sub2(S2[1], S2[3]);
    u64 C2_0 = sub2(B4[0], B4[2]), C2_1 = sub2(B4[1], B4[3]);
    u64 P7  = sub2(S21_0, S21_1);                   // parity(r & 0b0111), summed over bit3
    u64 P15 = sub2(C2_0, C2_1);                     // parity(r & 0b1111)
    u64 P14 = add2(C2_0, C2_1);                     // parity(r & 0b1110)
    u64 P12 = add2(add2(B4[0], B4[1]), add2(B4[2], B4[3]));   // parity(r & 0b1100)

    const int warp = t >> 5;
    const unsigned fullmask = 0xffffffffu;
    #pragma unroll
    for (int w = 0; w < NQ; ++w) {
        const int k = 9 - w;
        const unsigned mask = (k == 9) ? 0x1FFu : (0x3FFu & ~((1u << k) - 1u));
        const unsigned mr = (mask >> 6) & 15u, mt = mask & 63u;
        u64 acc = (mr == 15u) ? P15 : (mr == 14u) ? P14 : (mr == 12u) ? P12 : P7;
        if (__popc((unsigned)t & mt) & 1) acc = neg2(acc);
        #pragma unroll
        for (int off = 16; off; off >>= 1) {
            u64 o = __shfl_xor_sync(fullmask, acc, off);
            acc = add2(acc, o);
        }
        if ((t & 31) == 0) wred[warp][w] = acc;
    }
    __syncthreads();
    if (t < NQ) {
        u64 s = add2(wred[0][t], wred[1][t]);
        float ra, rb; upk2(s, ra, rb);
        out[b0 * NQ + t] = ra;
        out[b1 * NQ + t] = rb;
    }
}

extern "C" void kernel_launch(void* const* d_in, const int* in_sizes, int n_in,
                              void* d_out, int out_size) {
    const float* x      = (const float*)d_in[0];   // (16384, 10) float32
    const float* weight = (const float*)d_in[1];   // (4, 10, 3)  float32
    float* out          = (float*)d_out;           // (16384, 10) float32
    const int batch  = in_sizes[0] / NQ;
    const int blocks = batch / 2;                  // 2 batch elems per block
    quantum_layer_kernel<<<blocks, NT>>>(x, weight, out);
}

// round 12
// speedup vs baseline: 1.1128x; 1.0235x over previous
#include <cuda_runtime.h>

#define NQ       10
#define DIM      1024
#define NLAYERS  4
#define NT       64           // 64 threads = 2 warps = one state-pair (2 batch elems)
#define PI_F     3.14159265358979323846f

typedef unsigned long long u64;

// ---- packed f32x2 helpers (batch0 in lo, batch1 in hi) ----
__device__ __forceinline__ u64 pk2(float lo, float hi) {
    u64 r; asm("mov.b64 %0, {%1, %2};" : "=l"(r) : "f"(lo), "f"(hi)); return r;
}
__device__ __forceinline__ void upk2(u64 v, float& lo, float& hi) {
    asm("mov.b64 {%0, %1}, %2;" : "=f"(lo), "=f"(hi) : "l"(v));
}
__device__ __forceinline__ u64 fma2(u64 a, u64 b, u64 c) {
    u64 d; asm("fma.rn.f32x2 %0, %1, %2, %3;" : "=l"(d) : "l"(a), "l"(b), "l"(c)); return d;
}
__device__ __forceinline__ u64 mul2(u64 a, u64 b) {
    u64 d; asm("mul.rn.f32x2 %0, %1, %2;" : "=l"(d) : "l"(a), "l"(b)); return d;
}
__device__ __forceinline__ u64 add2(u64 a, u64 b) {
    u64 d; asm("add.rn.f32x2 %0, %1, %2;" : "=l"(d) : "l"(a), "l"(b)); return d;
}
__device__ __forceinline__ u64 neg2(u64 v) { return v ^ 0x8000000080000000ULL; }
__device__ __forceinline__ u64 sub2(u64 a, u64 b) { return add2(a, neg2(b)); }

// ---- scalar complex helpers (matrix construction only) ----
__device__ __forceinline__ float2 cmul(float2 a, float2 b) {
    return make_float2(fmaf(a.x, b.x, -a.y * b.y), fmaf(a.x, b.y, a.y * b.x));
}
__device__ __forceinline__ float2 cadd(float2 a, float2 b) { return make_float2(a.x + b.x, a.y + b.y); }
__device__ __forceinline__ float2 csub(float2 a, float2 b) { return make_float2(a.x - b.x, a.y - b.y); }
__device__ __forceinline__ float2 cscale(float s, float2 a) { return make_float2(s * a.x, s * a.y); }

// smem swizzle: phys(j) = j ^ s(j>>5), s(a) = (a&15) | ((a&8)<<1).
__device__ __forceinline__ int phys(int j) {
    int a = j >> 5;
    return j ^ ((a & 15) | ((a & 8) << 1));
}

// real RY on register bit g: 8 disjoint pairs, 8 packed ops/pair
#define APPLY_RY(COptr, g) do {                                             \
    const ulonglong2 q_ = *(COptr);                                         \
    const u64 c_ = q_.x, s_ = q_.y, ns_ = neg2(s_);                         \
    const int bm_ = 1 << (g), lo_ = bm_ - 1;                                \
    _Pragma("unroll") for (int p_ = 0; p_ < 8; ++p_) {                      \
        const int i0_ = ((p_ & ~lo_) << 1) | (p_ & lo_);                    \
        const int i1_ = i0_ | bm_;                                          \
        u64 b0r = fma2(c_, re[i0_], mul2(ns_, re[i1_]));                    \
        u64 b0i = fma2(c_, im[i0_], mul2(ns_, im[i1_]));                    \
        u64 b1r = fma2(c_, re[i1_], mul2(s_,  re[i0_]));                    \
        u64 b1i = fma2(c_, im[i1_], mul2(s_,  im[i0_]));                    \
        re[i0_] = b0r; im[i0_] = b0i; re[i1_] = b1r; im[i1_] = b1i;         \
    }                                                                       \
} while (0)

// ---- diagonal event, gray-code running-product version (no 32-reg table) ----
// Two interleaved chains: X covers regs 0..7 (bits 0..2), Y covers regs 8..15
// (= X * F3). (wr, wi, nwi) per chain; nwi = -wi tracked to avoid neg2 in cmuls.

#define DIAG_APPLY_X(g_) do {                                               \
    u64 ar_ = fma2(re[g_], xr_, mul2(im[g_], nxi_));                        \
    u64 ai_ = fma2(re[g_], xi_, mul2(im[g_], xr_));                         \
    re[g_] = ar_; im[g_] = ai_; } while (0)

#define DIAG_APPLY_Y(g_) do {                                               \
    u64 ar_ = fma2(re[g_], yr_, mul2(im[g_], nyi_));                        \
    u64 ai_ = fma2(re[g_], yi_, mul2(im[g_], yr_));                         \
    re[g_] = ar_; im[g_] = ai_; } while (0)

#define DIAG_UPD_SET_X(F_) do {                                             \
    u64 nr_ = fma2(xr_, (F_).x, mul2(nxi_, (F_).y));                        \
    u64 ni_ = fma2(xr_, (F_).y, mul2(xi_,  (F_).x));                        \
    xr_ = nr_; xi_ = ni_; nxi_ = neg2(ni_); } while (0)

#define DIAG_UPD_CLR_X(F_) do {                                             \
    u64 nr_ = fma2(xr_, (F_).x, mul2(xi_, (F_).y));                         \
    u64 ni_ = fma2(xi_, (F_).x, mul2(xr_, neg2((F_).y)));                   \
    xr_ = nr_; xi_ = ni_; nxi_ = neg2(ni_); } while (0)

#define DIAG_UPD_SET_Y(F_) do {                                             \
    u64 nr_ = fma2(yr_, (F_).x, mul2(nyi_, (F_).y));                        \
    u64 ni_ = fma2(yr_, (F_).y, mul2(yi_,  (F_).x));                        \
    yr_ = nr_; yi_ = ni_; nyi_ = neg2(ni_); } while (0)

#define DIAG_UPD_CLR_Y(F_) do {                                             \
    u64 nr_ = fma2(yr_, (F_).x, mul2(yi_, (F_).y));                         \
    u64 ni_ = fma2(yi_, (F_).x, mul2(yr_, neg2((F_).y)));                   \
    yr_ = nr_; yi_ = ni_; nyi_ = neg2(ni_); } while (0)

// gray walk over 3 bits: 0,1,3,2,6,7,5,4 (transitions: b0+,b1+,b0-,b2+,b0+,b1-,b0-)
#define APPLY_DIAG(FB, TW0, RW0) do {                                       \
    u64 xr_ = pk2(1.0f, 1.0f), xi_ = 0ULL, nxi_ = neg2(0ULL);               \
    _Pragma("unroll") for (int k_ = 0; k_ < 6; ++k_) {                      \
        const ulonglong2 f_ = (FB)[(TW0) - k_];                             \
        u64 nr_ = fma2(xr_, f_.x, mul2(nxi_, f_.y));                        \
        u64 ni_ = fma2(xr_, f_.y, mul2(xi_,  f_.x));                        \
        if ((t >> k_) & 1) { xr_ = nr_; xi_ = ni_; nxi_ = neg2(ni_); }      \
    }                                                                       \
    const ulonglong2 F0_ = (FB)[(RW0)];                                     \
    const ulonglong2 F1_ = (FB)[(RW0) - 1];                                 \
    const ulonglong2 F2_ = (FB)[(RW0) - 2];                                 \
    const ulonglong2 F3_ = (FB)[(RW0) - 3];                                 \
    u64 yr_ = fma2(xr_, F3_.x, mul2(nxi_, F3_.y));                          \
    u64 yi_ = fma2(xr_, F3_.y, mul2(xi_,  F3_.x));                          \
    u64 nyi_ = neg2(yi_);                                                   \
    DIAG_APPLY_X(0);                      DIAG_APPLY_Y(8);                  \
    DIAG_UPD_SET_X(F0_); DIAG_APPLY_X(1); DIAG_UPD_SET_Y(F0_); DIAG_APPLY_Y(9);  \
    DIAG_UPD_SET_X(F1_); DIAG_APPLY_X(3); DIAG_UPD_SET_Y(F1_); DIAG_APPLY_Y(11); \
    DIAG_UPD_CLR_X(F0_); DIAG_APPLY_X(2); DIAG_UPD_CLR_Y(F0_); DIAG_APPLY_Y(10); \
    DIAG_UPD_SET_X(F2_); DIAG_APPLY_X(6); DIAG_UPD_SET_Y(F2_); DIAG_APPLY_Y(14); \
    DIAG_UPD_SET_X(F0_); DIAG_APPLY_X(7); DIAG_UPD_SET_Y(F0_); DIAG_APPLY_Y(15); \
    DIAG_UPD_CLR_X(F1_); DIAG_APPLY_X(5); DIAG_UPD_CLR_Y(F1_); DIAG_APPLY_Y(13); \
    DIAG_UPD_CLR_X(F0_); DIAG_APPLY_X(4); DIAG_UPD_CLR_Y(F0_); DIAG_APPLY_Y(12); \
} while (0)

__global__ __launch_bounds__(NT, 8)
void quantum_layer_kernel(const float* __restrict__ x,
                          const float* __restrict__ weight,
                          float* __restrict__ out)
{
    __shared__ ulonglong2 sv[DIM];            // 16 KB: (re_pk2, im_pk2)
    __shared__ ulonglong2 ry[NLAYERS][NQ];    // (c, s) RY(delta) coeffs, packed
    __shared__ ulonglong2 Fe[NLAYERS][NQ];    // e^{i*eps_w}  (cos, sin), packed
    __shared__ ulonglong2 Fg[NLAYERS][NQ];    // e^{i*gamma_w}
    __shared__ unsigned short scat[DIM];      // CNOT-ring scatter LUT (swizzled)
    __shared__ u64 wred[2][NQ];               // cross-warp measurement reduce

    const int t  = threadIdx.x;               // 0..63
    const int b0 = blockIdx.x * 2, b1 = b0 + 1;

    // ---- CNOT-ring: st'[j] = st[p(j)]. scat[p(j)] = phys(j).
    for (int j = t; j < DIM; j += NT) {
        int src = j;
        src ^= (src & 1) << 9;                         // CNOT(9,0)
        #pragma unroll
        for (int q = 8; q >= 0; --q) {                 // CNOT(q,q+1)
            int cb = 9 - q, tb = 8 - q;
            src ^= ((src >> cb) & 1) << tb;
        }
        scat[src] = (unsigned short)phys(j);
    }

    // ---- per-wire ZYZ: M = RZ(gamma)*RY(delta)*RZ(eps) (scalar prefactors are
    // global phases, dropped). c=|m00|, s=|m10|, gamma=av-au, eps=-av-au.
    if (t < NQ) {
        const int w = t;
        float ang[2];
        ang[0] = tanhf(x[b0 * NQ + w]) * PI_F;
        ang[1] = tanhf(x[b1 * NQ + w]) * PI_F;
        for (int l = 0; l < NLAYERS; ++l) {
            float th1 = weight[(l * NQ + w) * 3 + 0];
            float th2 = weight[(l * NQ + w) * 3 + 1];
            float th3 = weight[(l * NQ + w) * 3 + 2];
            float cc[2], ss[2], ger[2], gei[2], eer[2], eei[2];
            #pragma unroll
            for (int bb = 0; bb < 2; ++bb) {
                float s0, c0, s1, c1, s2, c2, s3, c3;
                __sincosf(0.5f * ang[bb], &s0, &c0);
                __sincosf(0.5f * th1, &s1, &c1);
                __sincosf(0.5f * th2, &s2, &c2);
                __sincosf(0.5f * th3, &s3, &c3);
                float2 d1m = make_float2(c1, -s1), d1p = make_float2(c1, s1);
                float2 d3m = make_float2(c3, -s3), d3p = make_float2(c3, s3);
                // u = m00, v = m10 of the fused SU(2) matrix
                float2 u = cmul(d3m, csub(cscale(c2 * c0, d1m), cscale(s2 * s0, d1p)));
                float2 v = cmul(d3p, cadd(cscale(s2 * c0, d1m), cscale(c2 * s0, d1p)));
                cc[bb] = sqrtf(fmaf(u.x, u.x, u.y * u.y));
                ss[bb] = sqrtf(fmaf(v.x, v.x, v.y * v.y));
                float au = atan2f(u.y, u.x);
                float av = atan2f(v.y, v.x);
                float sg, cg, se, ce;
                __sincosf(av - au, &sg, &cg);    // e^{i*gamma}
                __sincosf(-av - au, &se, &ce);   // e^{i*eps}
                ger[bb] = cg; gei[bb] = sg; eer[bb] = ce; eei[bb] = se;
            }
            ry[l][w] = make_ulonglong2(pk2(cc[0], cc[1]), pk2(ss[0], ss[1]));
            Fg[l][w] = make_ulonglong2(pk2(ger[0], ger[1]), pk2(gei[0], gei[1]));
            Fe[l][w] = make_ulonglong2(pk2(eer[0], eer[1]), pk2(eei[0], eei[1]));
        }
    }
    __syncthreads();

    // ---- state: 16 amps/thread, three arrangements per layer:
    //  A: j = (t<<4)|r                 r bits 0..3 = wires 9..6; t bits 0..5 = wires 5..0
    //  B: j = (t>>4)<<8|(r<<4)|(t&15)  r bits 0..3 = wires 5..2
    //  C: j = (r<<6)|t                 r bits 0..3 = wires 3..0; t bits 0..5 = wires 9..4
    //     (C-group RY gates act on wires 1,0 = reg bits 2,3)
    u64 re[16], im[16];

    const int tbhi = (t >> 4) << 8, tblo = t & 15;

    #pragma unroll 1
    for (int l = 0; l < NLAYERS; ++l) {
        // ===== arrangement A: D_eps(l) (l>=1; eps_0 is a global phase), RY wires 9..6
        if (l == 0) {
            // |0..0>: pure-RY column-0 products on thread 0 (real)
            #pragma unroll
            for (int i = 0; i < 16; ++i) { re[i] = 0ULL; im[i] = 0ULL; }
            if (t == 0) {
                #pragma unroll
                for (int r = 0; r < 16; ++r) {
                    u64 v = pk2(1.0f, 1.0f);
                    #pragma unroll
                    for (int g = 0; g < 4; ++g) {
                        const ulonglong2 q = ry[0][9 - g];
                        v = mul2(v, ((r >> g) & 1) ? q.y : q.x);
                    }
                    re[r] = v;
                }
            }
        } else {
            #pragma unroll
            for (int r = 0; r < 16; ++r) {
                ulonglong2 v = sv[phys((t << 4) | r)];
                re[r] = v.x; im[r] = v.y;
            }
            APPLY_DIAG(&Fe[l][0], 5, 9);       // eps: t bits->wires 5..0, r bits->wires 9..6
            APPLY_RY(&ry[l][9], 0);
            APPLY_RY(&ry[l][8], 1);
            APPLY_RY(&ry[l][7], 2);
            APPLY_RY(&ry[l][6], 3);
        }
        #pragma unroll
        for (int r = 0; r < 16; ++r)
            sv[phys((t << 4) | r)] = make_ulonglong2(re[r], im[r]);
        __syncthreads();

        // ===== arrangement B: RY wires 5..2
        #pragma unroll
        for (int r = 0; r < 16; ++r) {
            ulonglong2 v = sv[phys(tbhi | (r << 4) | tblo)];
            re[r] = v.x; im[r] = v.y;
        }
        APPLY_RY(&ry[l][5], 0);
        APPLY_RY(&ry[l][4], 1);
        APPLY_RY(&ry[l][3], 2);
        APPLY_RY(&ry[l][2], 3);
        #pragma unroll
        for (int r = 0; r < 16; ++r)
            sv[phys(tbhi | (r << 4) | tblo)] = make_ulonglong2(re[r], im[r]);
        __syncthreads();

        // ===== arrangement C: RY wires 1,0; D_gamma(l) (l<=2; gamma_3 invisible in |.|^2)
        #pragma unroll
        for (int r = 0; r < 16; ++r) {
            ulonglong2 v = sv[phys((r << 6) | t)];
            re[r] = v.x; im[r] = v.y;
        }
        APPLY_RY(&ry[l][1], 2);
        APPLY_RY(&ry[l][0], 3);
        if (l < NLAYERS - 1) {
            APPLY_DIAG(&Fg[l][0], 9, 3);       // gamma: t->wires 9..4, r->wires 3..0
            __syncthreads();                   // all C loads done before scatter
            #pragma unroll
            for (int r = 0; r < 16; ++r)
                sv[scat[(r << 6) | t]] = make_ulonglong2(re[r], im[r]);
            __syncthreads();
        }
    }

    // ---- measurement in arrangement C: amp x = (r<<6)|t.
    // Final CNOT ring folded into signs: sign_w(x) = parity(x & mask_{9-w}),
    // mask_k = bits k..9 (k<=8), mask_9 = 0x1FF.
    #pragma unroll
    for (int i = 0; i < 16; ++i)
        re[i] = fma2(re[i], re[i], mul2(im[i], im[i]));   // packed |amp|^2

    // r-parity partial sums: only mr in {15,14,12,7} occur.
    u64 S[8], A[8];
    #pragma unroll
    for (int i = 0; i < 8; ++i) { S[i] = add2(re[i], re[i + 8]); A[i] = sub2(re[i], re[i + 8]); }
    u64 S2[4], B4[4];
    #pragma unroll
    for (int i = 0; i < 4; ++i) { S2[i] = sub2(S[i], S[i + 4]); B4[i] = sub2(A[i], A[i + 4]); }
    u64 S21_0 = sub2(S2[0], S2[2]), S21_1 = sub2(S2[1], S2[3]);
    u64 C2_0 = sub2(B4[0], B4[2]), C2_1 = sub2(B4[1], B4[3]);
    u64 P7  = sub2(S21_0, S21_1);                   // parity(r & 0b0111), summed over bit3
    u64 P15 = sub2(C2_0, C2_1);                     // parity(r & 0b1111)
    u64 P14 = add2(C2_0, C2_1);                     // parity(r & 0b1110)
    u64 P12 = add2(add2(B4[0], B4[1]), add2(B4[2], B4[3]));   // parity(r & 0b1100)

    const int warp = t >> 5;
    const unsigned fullmask = 0xffffffffu;
    #pragma unroll
    for (int w = 0; w < NQ; ++w) {
        const int k = 9 - w;
        const unsigned mask = (k == 9) ? 0x1FFu : (0x3FFu & ~((1u << k) - 1u));
        const unsigned mr = (mask >> 6) & 15u, mt = mask & 63u;
        u64 acc = (mr == 15u) ? P15 : (mr == 14u) ? P14 : (mr == 12u) ? P12 : P7;
        if (__popc((unsigned)t & mt) & 1) acc = neg2(acc);
        #pragma unroll
        for (int off = 16; off; off >>= 1) {
            u64 o = __shfl_xor_sync(fullmask, acc, off);
            acc = add2(acc, o);
        }
        if ((t & 31) == 0) wred[warp][w] = acc;
    }
    __syncthreads();
    if (t < NQ) {
        u64 s = add2(wred[0][t], wred[1][t]);
        float ra, rb; upk2(s, ra, rb);
        out[b0 * NQ + t] = ra;
        out[b1 * NQ + t] = rb;
    }
}

extern "C" void kernel_launch(void* const* d_in, const int* in_sizes, int n_in,
                              void* d_out, int out_size) {
    const float* x      = (const float*)d_in[0];   // (16384, 10) float32
    const float* weight = (const float*)d_in[1];   // (4, 10, 3)  float32
    float* out          = (float*)d_out;           // (16384, 10) float32
    const int batch  = in_sizes[0] / NQ;
    const int blocks = batch / 2;                  // 2 batch elems per block
    quantum_layer_kernel<<<blocks, NT>>>(x, weight, out);
}

// round 13
// speedup vs baseline: 1.2229x; 1.0989x over previous
#include <cuda_runtime.h>

#define NQ       10
#define DIM      1024
#define NLAYERS  4
#define NT       64           // 64 threads = 2 warps = one state-pair (2 batch elems)
#define PI_F     3.14159265358979323846f

typedef unsigned long long u64;

// ---- packed f32x2 helpers (batch0 in lo, batch1 in hi) ----
__device__ __forceinline__ u64 pk2(float lo, float hi) {
    u64 r; asm("mov.b64 %0, {%1, %2};" : "=l"(r) : "f"(lo), "f"(hi)); return r;
}
__device__ __forceinline__ void upk2(u64 v, float& lo, float& hi) {
    asm("mov.b64 {%0, %1}, %2;" : "=f"(lo), "=f"(hi) : "l"(v));
}
__device__ __forceinline__ u64 fma2(u64 a, u64 b, u64 c) {
    u64 d; asm("fma.rn.f32x2 %0, %1, %2, %3;" : "=l"(d) : "l"(a), "l"(b), "l"(c)); return d;
}
__device__ __forceinline__ u64 mul2(u64 a, u64 b) {
    u64 d; asm("mul.rn.f32x2 %0, %1, %2;" : "=l"(d) : "l"(a), "l"(b)); return d;
}
__device__ __forceinline__ u64 add2(u64 a, u64 b) {
    u64 d; asm("add.rn.f32x2 %0, %1, %2;" : "=l"(d) : "l"(a), "l"(b)); return d;
}
__device__ __forceinline__ u64 neg2(u64 v) { return v ^ 0x8000000080000000ULL; }
__device__ __forceinline__ u64 sub2(u64 a, u64 b) { return add2(a, neg2(b)); }

// ---- scalar complex helpers (matrix construction only) ----
__device__ __forceinline__ float2 cmul(float2 a, float2 b) {
    return make_float2(fmaf(a.x, b.x, -a.y * b.y), fmaf(a.x, b.y, a.y * b.x));
}
__device__ __forceinline__ float2 cadd(float2 a, float2 b) { return make_float2(a.x + b.x, a.y + b.y); }
__device__ __forceinline__ float2 csub(float2 a, float2 b) { return make_float2(a.x - b.x, a.y - b.y); }
__device__ __forceinline__ float2 cscale(float s, float2 a) { return make_float2(s * a.x, s * a.y); }

// ---- GF(2)-linear address machinery ----
// smem swizzle: physc(j) = j ^ s(j>>5), s(a) = (a&15)|((a&8)<<1). LINEAR over GF(2):
// physc(u ^ v) == physc(u) ^ physc(v). So every access = base(t) ^ constexpr-offset(r).
__host__ __device__ constexpr int physc(int j) {
    int a = j >> 5;
    return j ^ ((a & 15) | ((a & 8) << 1));
}
__host__ __device__ constexpr int par10(int v) {
    v ^= v >> 8; v ^= v >> 4; v ^= v >> 2; v ^= v >> 1; return v & 1;
}
// CNOT-ring inverse permutation (linear; masks validated by measurement path)
__host__ __device__ constexpr int pinv10(int x) {
    int r = 0;
    for (int k = 0; k < 10; ++k) {
        int m = (k == 9) ? 0x1FF : (0x3FF & ~((1 << k) - 1));
        r |= par10(x & m) << k;
    }
    return r;
}
// scatter address: st'[j]=st[p(j)] scattered as sv[physc(pinv(x))] = amp_x. Linear.
__host__ __device__ constexpr int scatAddr(int x) { return physc(pinv10(x)); }

// real RY on register bit g: 8 disjoint pairs, 8 packed ops/pair
#define APPLY_RY(COptr, g) do {                                             \
    const ulonglong2 q_ = *(COptr);                                         \
    const u64 c_ = q_.x, s_ = q_.y, ns_ = neg2(s_);                         \
    const int bm_ = 1 << (g), lo_ = bm_ - 1;                                \
    _Pragma("unroll") for (int p_ = 0; p_ < 8; ++p_) {                      \
        const int i0_ = ((p_ & ~lo_) << 1) | (p_ & lo_);                    \
        const int i1_ = i0_ | bm_;                                          \
        u64 b0r = fma2(c_, re[i0_], mul2(ns_, re[i1_]));                    \
        u64 b0i = fma2(c_, im[i0_], mul2(ns_, im[i1_]));                    \
        u64 b1r = fma2(c_, re[i1_], mul2(s_,  re[i0_]));                    \
        u64 b1i = fma2(c_, im[i1_], mul2(s_,  im[i0_]));                    \
        re[i0_] = b0r; im[i0_] = b0i; re[i1_] = b1r; im[i1_] = b1i;         \
    }                                                                       \
} while (0)

// ---- diagonal event: gray-code running products, conj handled via tables ----
#define DIAG_APPLY_X(g_) do {                                               \
    u64 ar_ = fma2(re[g_], xr_, mul2(im[g_], nxi_));                        \
    u64 ai_ = fma2(re[g_], xi_, mul2(im[g_], xr_));                         \
    re[g_] = ar_; im[g_] = ai_; } while (0)

#define DIAG_APPLY_Y(g_) do {                                               \
    u64 ar_ = fma2(re[g_], yr_, mul2(im[g_], nyi_));                        \
    u64 ai_ = fma2(re[g_], yi_, mul2(im[g_], yr_));                         \
    re[g_] = ar_; im[g_] = ai_; } while (0)

#define DIAG_UPD_X(F_) do {                                                 \
    u64 nr_ = fma2(xr_, (F_).x, mul2(nxi_, (F_).y));                        \
    u64 ni_ = fma2(xr_, (F_).y, mul2(xi_,  (F_).x));                        \
    xr_ = nr_; xi_ = ni_; nxi_ = neg2(ni_); } while (0)

#define DIAG_UPD_Y(F_) do {                                                 \
    u64 nr_ = fma2(yr_, (F_).x, mul2(nyi_, (F_).y));                        \
    u64 ni_ = fma2(yr_, (F_).y, mul2(yi_,  (F_).x));                        \
    yr_ = nr_; yi_ = ni_; nyi_ = neg2(ni_); } while (0)

// gray walk over 3 bits: 0,1,3,2,6,7,5,4. CLR transitions use conj table (FBc).
#define APPLY_DIAG(FB, FBc, TW0, RW0) do {                                  \
    u64 xr_ = pk2(1.0f, 1.0f), xi_ = 0ULL, nxi_ = neg2(0ULL);               \
    _Pragma("unroll") for (int k_ = 0; k_ < 6; ++k_) {                      \
        const ulonglong2 f_ = (FB)[(TW0) - k_];                             \
        u64 nr_ = fma2(xr_, f_.x, mul2(nxi_, f_.y));                        \
        u64 ni_ = fma2(xr_, f_.y, mul2(xi_,  f_.x));                        \
        if ((t >> k_) & 1) { xr_ = nr_; xi_ = ni_; nxi_ = neg2(ni_); }      \
    }                                                                       \
    const ulonglong2 F0_ = (FB)[(RW0)];                                     \
    const ulonglong2 F1_ = (FB)[(RW0) - 1];                                 \
    const ulonglong2 F2_ = (FB)[(RW0) - 2];                                 \
    const ulonglong2 F3_ = (FB)[(RW0) - 3];                                 \
    const ulonglong2 G0_ = (FBc)[(RW0)];                                    \
    const ulonglong2 G1_ = (FBc)[(RW0) - 1];                                \
    u64 yr_ = fma2(xr_, F3_.x, mul2(nxi_, F3_.y));                          \
    u64 yi_ = fma2(xr_, F3_.y, mul2(xi_,  F3_.x));                          \
    u64 nyi_ = neg2(yi_);                                                   \
    DIAG_APPLY_X(0);                  DIAG_APPLY_Y(8);                      \
    DIAG_UPD_X(F0_); DIAG_APPLY_X(1); DIAG_UPD_Y(F0_); DIAG_APPLY_Y(9);     \
    DIAG_UPD_X(F1_); DIAG_APPLY_X(3); DIAG_UPD_Y(F1_); DIAG_APPLY_Y(11);    \
    DIAG_UPD_X(G0_); DIAG_APPLY_X(2); DIAG_UPD_Y(G0_); DIAG_APPLY_Y(10);    \
    DIAG_UPD_X(F2_); DIAG_APPLY_X(6); DIAG_UPD_Y(F2_); DIAG_APPLY_Y(14);    \
    DIAG_UPD_X(F0_); DIAG_APPLY_X(7); DIAG_UPD_Y(F0_); DIAG_APPLY_Y(15);    \
    DIAG_UPD_X(G1_); DIAG_APPLY_X(5); DIAG_UPD_Y(G1_); DIAG_APPLY_Y(13);    \
    DIAG_UPD_X(G0_); DIAG_APPLY_X(4); DIAG_UPD_Y(G0_); DIAG_APPLY_Y(12);    \
} while (0)

__global__ __launch_bounds__(NT, 9)
void quantum_layer_kernel(const float* __restrict__ x,
                          const float* __restrict__ weight,
                          float* __restrict__ out)
{
    __shared__ ulonglong2 sv[DIM];            // 16 KB: (re_pk2, im_pk2)
    __shared__ ulonglong2 ry[NLAYERS][NQ];    // (c, s) RY(delta) coeffs, packed
    __shared__ ulonglong2 Fe[NLAYERS][NQ];    // e^{i*eps_w}  (cos, sin)
    __shared__ ulonglong2 FeC[NLAYERS][NQ];   // conj
    __shared__ ulonglong2 Fg[NLAYERS][NQ];    // e^{i*gamma_w}
    __shared__ ulonglong2 FgC[NLAYERS][NQ];   // conj
    __shared__ u64 wred[2][NQ];               // cross-warp measurement reduce

    const int t  = threadIdx.x;               // 0..63
    const int b0 = blockIdx.x * 2, b1 = b0 + 1;

    // ---- per-wire ZYZ: M = RZ(gamma)*RY(delta)*RZ(eps) (scalar prefactors are
    // global phases, dropped). c=|m00|, s=|m10|, gamma=av-au, eps=-av-au.
    if (t < NQ) {
        const int w = t;
        float ang[2];
        ang[0] = tanhf(x[b0 * NQ + w]) * PI_F;
        ang[1] = tanhf(x[b1 * NQ + w]) * PI_F;
        for (int l = 0; l < NLAYERS; ++l) {
            float th1 = weight[(l * NQ + w) * 3 + 0];
            float th2 = weight[(l * NQ + w) * 3 + 1];
            float th3 = weight[(l * NQ + w) * 3 + 2];
            float cc[2], ss[2], ger[2], gei[2], eer[2], eei[2];
            #pragma unroll
            for (int bb = 0; bb < 2; ++bb) {
                float s0, c0, s1, c1, s2, c2, s3, c3;
                __sincosf(0.5f * ang[bb], &s0, &c0);
                __sincosf(0.5f * th1, &s1, &c1);
                __sincosf(0.5f * th2, &s2, &c2);
                __sincosf(0.5f * th3, &s3, &c3);
                float2 d1m = make_float2(c1, -s1), d1p = make_float2(c1, s1);
                float2 d3m = make_float2(c3, -s3), d3p = make_float2(c3, s3);
                // u = m00, v = m10 of the fused SU(2) matrix
                float2 u = cmul(d3m, csub(cscale(c2 * c0, d1m), cscale(s2 * s0, d1p)));
                float2 v = cmul(d3p, cadd(cscale(s2 * c0, d1m), cscale(c2 * s0, d1p)));
                cc[bb] = sqrtf(fmaf(u.x, u.x, u.y * u.y));
                ss[bb] = sqrtf(fmaf(v.x, v.x, v.y * v.y));
                float au = atan2f(u.y, u.x);
                float av = atan2f(v.y, v.x);
                float sg, cg, se, ce;
                __sincosf(av - au, &sg, &cg);    // e^{i*gamma}
                __sincosf(-av - au, &se, &ce);   // e^{i*eps}
                ger[bb] = cg; gei[bb] = sg; eer[bb] = ce; eei[bb] = se;
            }
            ry[l][w]  = make_ulonglong2(pk2(cc[0], cc[1]), pk2(ss[0], ss[1]));
            u64 gr = pk2(ger[0], ger[1]), gi = pk2(gei[0], gei[1]);
            u64 er = pk2(eer[0], eer[1]), ei = pk2(eei[0], eei[1]);
            Fg[l][w]  = make_ulonglong2(gr, gi);
            FgC[l][w] = make_ulonglong2(gr, neg2(gi));
            Fe[l][w]  = make_ulonglong2(er, ei);
            FeC[l][w] = make_ulonglong2(er, neg2(ei));
        }
    }
    __syncthreads();

    // ---- linear address bases (one-time per thread); offsets are constexpr
    const int tbhi = (t >> 4) << 8, tblo = t & 15;
    const int baseA = physc(t << 4);        // A: addr = baseA ^ r           (physc(r)=r, r<16)
    const int baseB = physc(tbhi | tblo);   // B: addr = baseB ^ physc(r<<4)
    const int baseC = physc(t);             // C: addr = baseC ^ physc(r<<6)
    const int baseS = scatAddr(t);          // scatter: addr = baseS ^ scatAddr(r<<6)

    // ---- state: 16 amps/thread, three arrangements per layer:
    //  A: j = (t<<4)|r                 r bits 0..3 = wires 9..6; t bits 0..5 = wires 5..0
    //  B: j = tbhi|(r<<4)|tblo         r bits 0..3 = wires 5..2
    //  C: j = (r<<6)|t                 r bits 0..3 = wires 3..0; t bits 0..5 = wires 9..4
    u64 re[16], im[16];

    #pragma unroll 1
    for (int l = 0; l < NLAYERS; ++l) {
        // ===== arrangement A: D_eps(l) (l>=1; eps_0 is a global phase), RY wires 9..6
        if (l == 0) {
            // |0..0>: pure-RY column-0 products on thread 0 (real)
            #pragma unroll
            for (int i = 0; i < 16; ++i) { re[i] = 0ULL; im[i] = 0ULL; }
            if (t == 0) {
                #pragma unroll
                for (int r = 0; r < 16; ++r) {
                    u64 v = pk2(1.0f, 1.0f);
                    #pragma unroll
                    for (int g = 0; g < 4; ++g) {
                        const ulonglong2 q = ry[0][9 - g];
                        v = mul2(v, ((r >> g) & 1) ? q.y : q.x);
                    }
                    re[r] = v;
                }
            }
        } else {
            #pragma unroll
            for (int r = 0; r < 16; ++r) {
                ulonglong2 v = sv[baseA ^ r];
                re[r] = v.x; im[r] = v.y;
            }
            APPLY_DIAG(&Fe[l][0], &FeC[l][0], 5, 9);   // eps: t->wires 5..0, r->wires 9..6
            APPLY_RY(&ry[l][9], 0);
            APPLY_RY(&ry[l][8], 1);
            APPLY_RY(&ry[l][7], 2);
            APPLY_RY(&ry[l][6], 3);
        }
        #pragma unroll
        for (int r = 0; r < 16; ++r)
            sv[baseA ^ r] = make_ulonglong2(re[r], im[r]);
        __syncthreads();

        // ===== arrangement B: RY wires 5..2
        #pragma unroll
        for (int r = 0; r < 16; ++r) {
            ulonglong2 v = sv[baseB ^ physc(r << 4)];
            re[r] = v.x; im[r] = v.y;
        }
        APPLY_RY(&ry[l][5], 0);
        APPLY_RY(&ry[l][4], 1);
        APPLY_RY(&ry[l][3], 2);
        APPLY_RY(&ry[l][2], 3);
        #pragma unroll
        for (int r = 0; r < 16; ++r)
            sv[baseB ^ physc(r << 4)] = make_ulonglong2(re[r], im[r]);
        __syncthreads();

        // ===== arrangement C: RY wires 1,0; D_gamma(l) (l<=2; gamma_3 invisible in |.|^2)
        #pragma unroll
        for (int r = 0; r < 16; ++r) {
            ulonglong2 v = sv[baseC ^ physc(r << 6)];
            re[r] = v.x; im[r] = v.y;
        }
        APPLY_RY(&ry[l][1], 2);
        APPLY_RY(&ry[l][0], 3);
        if (l < NLAYERS - 1) {
            APPLY_DIAG(&Fg[l][0], &FgC[l][0], 9, 3);   // gamma: t->wires 9..4, r->wires 3..0
            __syncthreads();                   // all C loads done before permuted scatter
            #pragma unroll
            for (int r = 0; r < 16; ++r)
                sv[baseS ^ scatAddr(r << 6)] = make_ulonglong2(re[r], im[r]);
            __syncthreads();
        }
    }

    // ---- measurement in arrangement C: amp x = (r<<6)|t.
    // Final CNOT ring folded into signs: sign_w(x) = parity(x & mask_{9-w}),
    // mask_k = bits k..9 (k<=8), mask_9 = 0x1FF.
    #pragma unroll
    for (int i = 0; i < 16; ++i)
        re[i] = fma2(re[i], re[i], mul2(im[i], im[i]));   // packed |amp|^2

    // r-parity partial sums: only mr in {15,14,12,7} occur.
    u64 S[8], A[8];
    #pragma unroll
    for (int i = 0; i < 8; ++i) { S[i] = add2(re[i], re[i + 8]); A[i] = sub2(re[i], re[i + 8]); }
    u64 S2[4], B4[4];
    #pragma unroll
    for (int i = 0; i < 4; ++i) { S2[i] = sub2(S[i], S[i + 4]); B4[i] = sub2(A[i], A[i + 4]); }
    u64 S21_0 = sub2(S2[0], S2[2]), S21_1 = sub2(S2[1], S2[3]);
    u64 C2_0 = sub2(B4[0], B4[2]), C2_1 = sub2(B4[1], B4[3]);
    u64 P7  = sub2(S21_0, S21_1);                   // parity(r & 0b0111), summed over bit3
    u64 P15 = sub2(C2_0, C2_1);                     // parity(r & 0b1111)
    u64 P14 = add2(C2_0, C2_1);                     // parity(r & 0b1110)
    u64 P12 = add2(add2(B4[0], B4[1]), add2(B4[2], B4[3]));   // parity(r & 0b1100)

    const int warp = t >> 5;
    const unsigned fullmask = 0xffffffffu;
    #pragma unroll
    for (int w = 0; w < NQ; ++w) {
        const int k = 9 - w;
        const unsigned mask = (k == 9) ? 0x1FFu : (0x3FFu & ~((1u << k) - 1u));
        const unsigned mr = (mask >> 6) & 15u, mt = mask & 63u;
        u64 acc = (mr == 15u) ? P15 : (mr == 14u) ? P14 : (mr == 12u) ? P12 : P7;
        if (__popc((unsigned)t & mt) & 1) acc = neg2(acc);
        #pragma unroll
        for (int off = 16; off; off >>= 1) {
            u64 o = __shfl_xor_sync(fullmask, acc, off);
            acc = add2(acc, o);
        }
        if ((t & 31) == 0) wred[warp][w] = acc;
    }
    __syncthreads();
    if (t < NQ) {
        u64 s = add2(wred[0][t], wred[1][t]);
        float ra, rb; upk2(s, ra, rb);
        out[b0 * NQ + t] = ra;
        out[b1 * NQ + t] = rb;
    }
}

extern "C" void kernel_launch(void* const* d_in, const int* in_sizes, int n_in,
                              void* d_out, int out_size) {
    const float* x      = (const float*)d_in[0];   // (16384, 10) float32
    const float* weight = (const float*)d_in[1];   // (4, 10, 3)  float32
    float* out          = (float*)d_out;           // (16384, 10) float32
    const int batch  = in_sizes[0] / NQ;
    const int blocks = batch / 2;                  // 2 batch elems per block
    quantum_layer_kernel<<<blocks, NT>>>(x, weight, out);
}